// round 13
// baseline (speedup 1.0000x reference)
#include <cuda_runtime.h>

// Problem constants (fixed by the dataset)
#define T_LEN 4096
#define B_SZ  32
#define C_SZ  300
#define W_SZ  128
#define C4    (C_SZ / 4)     // 75 float4 per (t,b) row
#define ROW4  (B_SZ * C4)    // 2400 float4 per t-slice
#define NTHR  480            // 2400 = 480 * 5 exactly
#define UNROLL 5

// R8 frontier structure (confirmed 4x at 51.7us) with ONE ablation: the
// .cs (evict-first) cache ops on the x-load / out-store stream are replaced
// by default write-back ld/st. Hypothesis: evict-first writebacks force
// frequent small HBM write bursts, raising read/write turnaround overhead —
// the very mix penalty pinning DRAM at ~70%. Default policy lets L2 batch
// dirty lines into longer write bursts. pe stays __ldcg (L2-only, no L1
// pollution). Everything else is byte-identical to the measured optimum.
__global__ void __launch_bounds__(NTHR) k_fused(const float4* __restrict__ x,
                                                const float4* __restrict__ pe,
                                                const int*    __restrict__ dur,
                                                float4*       __restrict__ out) {
    __shared__ int s_pos[B_SZ];
    const int t    = blockIdx.x;
    const int warp = threadIdx.x >> 5;
    const int lane = threadIdx.x & 31;
    const int tid  = threadIdx.x;

    // ---- prologue: segment position for 4 samples per warp (warps 0-7) ----
    if (warp < 8) {
#pragma unroll
        for (int k = 0; k < 4; k++) {
            const int b = warp * 4 + k;
            int4 d4 = __ldg((const int4*)(dur + b * W_SZ + lane * 4));
            int s = d4.x + d4.y + d4.z + d4.w;
            int incl = s;
#pragma unroll
            for (int o = 1; o < 32; o <<= 1) {
                int vv = __shfl_up_sync(0xffffffffu, incl, o);
                if (lane >= o) incl += vv;
            }
            int base = incl - s;                   // exclusive prefix across lanes
            int st0 = base;
            int st1 = base + d4.x;
            int st2 = st1 + d4.y;
            int st3 = st2 + d4.z;
            int tot = __shfl_sync(0xffffffffu, incl, 31);

            // Largest start <= t: starts nondecreasing across lanes.
            unsigned m = __ballot_sync(0xffffffffu, st0 <= t);
            int L = 31 - __clz(m);
            int loc = st0;
            if (st1 <= t) loc = st1;
            if (st2 <= t) loc = st2;
            if (st3 <= t) loc = st3;
            int seg = __shfl_sync(0xffffffffu, loc, L);

            if (lane == 0) s_pos[b] = (t < tot) ? (t - seg) : -1;
        }
    }
    __syncthreads();

    // ---- streaming add: exact unroll, batched x loads for MLP ----
    const float4* xrow = x + (size_t)t * ROW4;
    float4*       orow = out + (size_t)t * ROW4;

    float4 v[UNROLL];
    int    bb[UNROLL], cc[UNROLL];
#pragma unroll
    for (int i = 0; i < UNROLL; i++) {
        int j = tid + i * NTHR;
        bb[i] = j / C4;                    // constant divide -> mul/shift
        cc[i] = j - bb[i] * C4;
        v[i]  = xrow[j];                   // default load (write-back aging)
    }
#pragma unroll
    for (int i = 0; i < UNROLL; i++) {
        int p = s_pos[bb[i]];
        if (p >= 0) {
            float4 pv = __ldcg(pe + p * C4 + cc[i]);  // L2-only: no L1 pollution
            v[i].x += pv.x; v[i].y += pv.y; v[i].z += pv.z; v[i].w += pv.w;
        }
    }
#pragma unroll
    for (int i = 0; i < UNROLL; i++) {
        orow[tid + i * NTHR] = v[i];       // default store (L2 write-back batching)
    }
}

extern "C" void kernel_launch(void* const* d_in, const int* in_sizes, int n_in,
                              void* d_out, int out_size) {
    const float* x  = (const float*)d_in[0];
    const float* pe = (const float*)d_in[1];
    const int*   du = (const int*)d_in[2];
    // d_in[3] = train flag, unused by the reference math.
    k_fused<<<T_LEN, NTHR>>>((const float4*)x, (const float4*)pe, du, (float4*)d_out);
}

// round 14
// speedup vs baseline: 1.0066x; 1.0066x over previous
#include <cuda_runtime.h>

// Problem constants (fixed by the dataset)
#define T_LEN 4096
#define B_SZ  32
#define C_SZ  300
#define W_SZ  128
#define C4    (C_SZ / 4)     // 75 float4 per (t,b) row
#define ROW4  (B_SZ * C4)    // 2400 float4 per t-slice
#define NTHR  480            // 2400 = 480 * 5 exactly
#define UNROLL 5

// R8 frontier structure; cache-policy quadrant (default load, .cs store).
// R13 showed default write-back STORES improve in-kernel BW (45.98us kernel,
// session best) but defer ~150MB of dirty-L2 writeback into the next graph
// replay (+2.4us total). .cs stores drain eagerly inside the kernel where
// the cost overlaps. Default LOADS are kept from R13 to retain the read-side
// gain. pe stays __ldcg (L2-only, no L1 pollution).
__global__ void __launch_bounds__(NTHR) k_fused(const float4* __restrict__ x,
                                                const float4* __restrict__ pe,
                                                const int*    __restrict__ dur,
                                                float4*       __restrict__ out) {
    __shared__ int s_pos[B_SZ];
    const int t    = blockIdx.x;
    const int warp = threadIdx.x >> 5;
    const int lane = threadIdx.x & 31;
    const int tid  = threadIdx.x;

    // ---- prologue: segment position for 4 samples per warp (warps 0-7) ----
    if (warp < 8) {
#pragma unroll
        for (int k = 0; k < 4; k++) {
            const int b = warp * 4 + k;
            int4 d4 = __ldg((const int4*)(dur + b * W_SZ + lane * 4));
            int s = d4.x + d4.y + d4.z + d4.w;
            int incl = s;
#pragma unroll
            for (int o = 1; o < 32; o <<= 1) {
                int vv = __shfl_up_sync(0xffffffffu, incl, o);
                if (lane >= o) incl += vv;
            }
            int base = incl - s;                   // exclusive prefix across lanes
            int st0 = base;
            int st1 = base + d4.x;
            int st2 = st1 + d4.y;
            int st3 = st2 + d4.z;
            int tot = __shfl_sync(0xffffffffu, incl, 31);

            // Largest start <= t: starts nondecreasing across lanes.
            unsigned m = __ballot_sync(0xffffffffu, st0 <= t);
            int L = 31 - __clz(m);
            int loc = st0;
            if (st1 <= t) loc = st1;
            if (st2 <= t) loc = st2;
            if (st3 <= t) loc = st3;
            int seg = __shfl_sync(0xffffffffu, loc, L);

            if (lane == 0) s_pos[b] = (t < tot) ? (t - seg) : -1;
        }
    }
    __syncthreads();

    // ---- streaming add: exact unroll, batched x loads for MLP ----
    const float4* xrow = x + (size_t)t * ROW4;
    float4*       orow = out + (size_t)t * ROW4;

    float4 v[UNROLL];
    int    bb[UNROLL], cc[UNROLL];
#pragma unroll
    for (int i = 0; i < UNROLL; i++) {
        int j = tid + i * NTHR;
        bb[i] = j / C4;                    // constant divide -> mul/shift
        cc[i] = j - bb[i] * C4;
        v[i]  = xrow[j];                   // default load (read-side gain, R13)
    }
#pragma unroll
    for (int i = 0; i < UNROLL; i++) {
        int p = s_pos[bb[i]];
        if (p >= 0) {
            float4 pv = __ldcg(pe + p * C4 + cc[i]);  // L2-only: no L1 pollution
            v[i].x += pv.x; v[i].y += pv.y; v[i].z += pv.z; v[i].w += pv.w;
        }
    }
#pragma unroll
    for (int i = 0; i < UNROLL; i++) {
        __stcs(orow + tid + i * NTHR, v[i]);  // .cs store: eager in-kernel drain
    }
}

extern "C" void kernel_launch(void* const* d_in, const int* in_sizes, int n_in,
                              void* d_out, int out_size) {
    const float* x  = (const float*)d_in[0];
    const float* pe = (const float*)d_in[1];
    const int*   du = (const int*)d_in[2];
    // d_in[3] = train flag, unused by the reference math.
    k_fused<<<T_LEN, NTHR>>>((const float4*)x, (const float4*)pe, du, (float4*)d_out);
}

// round 15
// speedup vs baseline: 1.0309x; 1.0241x over previous
#include <cuda_runtime.h>

// Problem constants (fixed by the dataset)
#define T_LEN 4096
#define B_SZ  32
#define C_SZ  300
#define W_SZ  128
#define C4    (C_SZ / 4)     // 75 float4 per (t,b) row
#define ROW4  (B_SZ * C4)    // 2400 float4 per t-slice
#define NTHR  480            // 2400 = 480 * 5 exactly
#define UNROLL 5

// FINAL kernel — measured optimum, reproduced 4x at 51.68-51.71us.
// One block per t. Warps 0-7 compute the 32 per-sample segment positions
// (warp-scan of durations + ballot select of "largest start <= t"); then a
// 3-phase stream: batched __ldcs x-loads (MLP=5), branched __ldcg pe gather
// + add (L2-only, zero intra-block reuse), batched __stcs stores (eager
// in-kernel drain; default write-back defers ~150MB of dirty-L2 into the
// next graph replay, R13/R14). regs=32, occ~78%, DRAM ~70% = the HBM
// read/write-mix turnaround ceiling (~5.6 TB/s) on this chip.
//
// Falsified alternatives (all slower): reg-hoisted loads (R4 52.3, occ
// collapse), T_PER=2 (R5 53.7, regs 44), cp.async staging (R6 53.8, smem
// round-trip), branchless pe (R7 55.4, +50% gathers), merged add+store
// (R9 53.3, STG inside branch), persistent blocks (R11 63.5, barrier
// lockstep), default-policy loads/stores (R13 53.3, R14 53.0).
__global__ void __launch_bounds__(NTHR) k_fused(const float4* __restrict__ x,
                                                const float4* __restrict__ pe,
                                                const int*    __restrict__ dur,
                                                float4*       __restrict__ out) {
    __shared__ int s_pos[B_SZ];
    const int t    = blockIdx.x;
    const int warp = threadIdx.x >> 5;
    const int lane = threadIdx.x & 31;
    const int tid  = threadIdx.x;

    // ---- prologue: segment position for 4 samples per warp (warps 0-7) ----
    if (warp < 8) {
#pragma unroll
        for (int k = 0; k < 4; k++) {
            const int b = warp * 4 + k;
            int4 d4 = __ldg((const int4*)(dur + b * W_SZ + lane * 4));
            int s = d4.x + d4.y + d4.z + d4.w;
            int incl = s;
#pragma unroll
            for (int o = 1; o < 32; o <<= 1) {
                int vv = __shfl_up_sync(0xffffffffu, incl, o);
                if (lane >= o) incl += vv;
            }
            int base = incl - s;                   // exclusive prefix across lanes
            int st0 = base;
            int st1 = base + d4.x;
            int st2 = st1 + d4.y;
            int st3 = st2 + d4.z;
            int tot = __shfl_sync(0xffffffffu, incl, 31);

            // Largest start <= t: starts nondecreasing across lanes.
            unsigned m = __ballot_sync(0xffffffffu, st0 <= t);
            int L = 31 - __clz(m);
            int loc = st0;
            if (st1 <= t) loc = st1;
            if (st2 <= t) loc = st2;
            if (st3 <= t) loc = st3;
            int seg = __shfl_sync(0xffffffffu, loc, L);

            if (lane == 0) s_pos[b] = (t < tot) ? (t - seg) : -1;
        }
    }
    __syncthreads();

    // ---- streaming add: exact unroll, batched x loads for MLP ----
    const float4* xrow = x + (size_t)t * ROW4;
    float4*       orow = out + (size_t)t * ROW4;

    float4 v[UNROLL];
    int    bb[UNROLL], cc[UNROLL];
#pragma unroll
    for (int i = 0; i < UNROLL; i++) {
        int j = tid + i * NTHR;
        bb[i] = j / C4;                    // constant divide -> mul/shift
        cc[i] = j - bb[i] * C4;
        v[i]  = __ldcs(xrow + j);          // streaming read (evict-first)
    }
#pragma unroll
    for (int i = 0; i < UNROLL; i++) {
        int p = s_pos[bb[i]];
        if (p >= 0) {
            float4 pv = __ldcg(pe + p * C4 + cc[i]);  // L2-only: no L1 pollution
            v[i].x += pv.x; v[i].y += pv.y; v[i].z += pv.z; v[i].w += pv.w;
        }
    }
#pragma unroll
    for (int i = 0; i < UNROLL; i++) {
        __stcs(orow + tid + i * NTHR, v[i]);          // streaming write
    }
}

extern "C" void kernel_launch(void* const* d_in, const int* in_sizes, int n_in,
                              void* d_out, int out_size) {
    const float* x  = (const float*)d_in[0];
    const float* pe = (const float*)d_in[1];
    const int*   du = (const int*)d_in[2];
    // d_in[3] = train flag, unused by the reference math.
    k_fused<<<T_LEN, NTHR>>>((const float4*)x, (const float4*)pe, du, (float4*)d_out);
}

// round 16
// speedup vs baseline: 1.0316x; 1.0006x over previous
#include <cuda_runtime.h>

// Problem constants (fixed by the dataset)
#define T_LEN 4096
#define B_SZ  32
#define C_SZ  300
#define W_SZ  128
#define C4    (C_SZ / 4)      // 75 float4 per (t,b) row
#define ROW4  (B_SZ * C4)     // 2400 float4 per t-slice
#define T_PER 2               // t-slices per block (contiguous stream)
#define NTHR  960             // 4800 float4 / 960 = 5 per thread (unchanged!)
#define UNROLL 5

// 2-slice variant of the R8 frontier. x/out are contiguous in [t][b][c], so
// a block covering t0..t0+1 streams 4800 consecutive float4 with the SAME
// per-thread shape as R8 (5 in-flight float4, regs ~32). The scan prologue
// + barrier is amortized over 2x bytes; s_pos becomes a 64-entry table
// indexed directly by j/75 (bit 5 = slice). All proven invariants kept:
// .cs stream, .ldcg pe gather, 3-phase body, independent blocks.
__global__ void __launch_bounds__(NTHR) k_fused(const float4* __restrict__ x,
                                                const float4* __restrict__ pe,
                                                const int*    __restrict__ dur,
                                                float4*       __restrict__ out) {
    __shared__ int s_pos[T_PER * B_SZ];    // [slice*32 + b]
    const int t0   = blockIdx.x * T_PER;
    const int warp = threadIdx.x >> 5;
    const int lane = threadIdx.x & 31;
    const int tid  = threadIdx.x;

    // ---- prologue: scan once, ballot-select per t (warps 0-7) ----
    if (warp < 8) {
#pragma unroll
        for (int k = 0; k < 4; k++) {
            const int b = warp * 4 + k;
            int4 d4 = __ldg((const int4*)(dur + b * W_SZ + lane * 4));
            int s = d4.x + d4.y + d4.z + d4.w;
            int incl = s;
#pragma unroll
            for (int o = 1; o < 32; o <<= 1) {
                int vv = __shfl_up_sync(0xffffffffu, incl, o);
                if (lane >= o) incl += vv;
            }
            int base = incl - s;                   // exclusive prefix across lanes
            int st0 = base;
            int st1 = base + d4.x;
            int st2 = st1 + d4.y;
            int st3 = st2 + d4.z;
            int tot = __shfl_sync(0xffffffffu, incl, 31);

#pragma unroll
            for (int tt = 0; tt < T_PER; tt++) {
                const int t = t0 + tt;
                // Largest start <= t: starts nondecreasing across lanes.
                unsigned m = __ballot_sync(0xffffffffu, st0 <= t);
                int L = 31 - __clz(m);
                int loc = st0;
                if (st1 <= t) loc = st1;
                if (st2 <= t) loc = st2;
                if (st3 <= t) loc = st3;
                int seg = __shfl_sync(0xffffffffu, loc, L);
                if (lane == 0) s_pos[tt * B_SZ + b] = (t < tot) ? (t - seg) : -1;
            }
        }
    }
    __syncthreads();

    // ---- streaming add over 4800 contiguous float4 (2 slices) ----
    const float4* xrow = x + (size_t)t0 * ROW4;
    float4*       orow = out + (size_t)t0 * ROW4;

    float4 v[UNROLL];
    int    bb[UNROLL], cc[UNROLL];
#pragma unroll
    for (int i = 0; i < UNROLL; i++) {
        int j = tid + i * NTHR;            // 0..4799
        bb[i] = j / C4;                    // 0..63: (slice<<5)|b — direct s_pos idx
        cc[i] = j - bb[i] * C4;
        v[i]  = __ldcs(xrow + j);          // streaming read (evict-first)
    }
#pragma unroll
    for (int i = 0; i < UNROLL; i++) {
        int p = s_pos[bb[i]];
        if (p >= 0) {
            float4 pv = __ldcg(pe + p * C4 + cc[i]);  // L2-only: no L1 pollution
            v[i].x += pv.x; v[i].y += pv.y; v[i].z += pv.z; v[i].w += pv.w;
        }
    }
#pragma unroll
    for (int i = 0; i < UNROLL; i++) {
        __stcs(orow + tid + i * NTHR, v[i]);          // streaming write
    }
}

extern "C" void kernel_launch(void* const* d_in, const int* in_sizes, int n_in,
                              void* d_out, int out_size) {
    const float* x  = (const float*)d_in[0];
    const float* pe = (const float*)d_in[1];
    const int*   du = (const int*)d_in[2];
    // d_in[3] = train flag, unused by the reference math.
    k_fused<<<T_LEN / T_PER, NTHR>>>((const float4*)x, (const float4*)pe, du,
                                     (float4*)d_out);
}